// round 6
// baseline (speedup 1.0000x reference)
#include <cuda_runtime.h>
#include <cstdint>

// Problem shape (fixed by the reference): B=8, S=512, V=32000, M=32, PAD_ID=1
// NOTE: jax without x64 silently makes "int64" inputs int32 — a and mask are int32.
#define BB 8
#define SS 512
#define VV 32000
#define MM 32
#define PAD_ID 1

__global__ void zero_out_kernel(float* out) {
    if (threadIdx.x < BB) out[threadIdx.x] = 0.0f;
}

// One warp per (b,s) row. Lane j handles mask[b,s,j].
// logp(b,s) = logits[b,s,a] - log( sum_{j: mask_j>0} exp(logits[b,s,mask_j]) )
// out[b] += logp * (a != PAD_ID)
__global__ void __launch_bounds__(256) masked_logp_kernel(
    const float* __restrict__ logits,   // [B,S,V] f32
    const int* __restrict__ a,          // [B,S]   i32
    const int* __restrict__ mask,       // [B,S,M] i32
    float* __restrict__ out)            // [B]     f32
{
    const int warps_per_block = blockDim.x >> 5;
    const int row = blockIdx.x * warps_per_block + (threadIdx.x >> 5);
    const int lane = threadIdx.x & 31;
    if (row >= BB * SS) return;

    const int b = row / SS;
    const float* __restrict__ lrow = logits + (size_t)row * VV;

    // Issue the action-token gather up-front on lane 0 so it overlaps the
    // mask gathers (both DRAM rounds in flight together -> ~1 latency round).
    const int ai = (lane == 0) ? __ldg(a + row) : 0;
    float la = 0.0f;
    bool take = false;
    if (lane == 0 && ai != PAD_ID) {
        take = true;
        la = __ldg(lrow + ai);
    }

    // Gather candidate logit for this lane's mask id.
    const int mid = __ldg(mask + (size_t)row * MM + lane);
    const bool valid = (mid > 0);
    float g = valid ? __ldg(lrow + mid) : -__int_as_float(0x7f800000); // -inf

    // Warp max over gathered logits.
    float m = g;
    #pragma unroll
    for (int o = 16; o > 0; o >>= 1)
        m = fmaxf(m, __shfl_xor_sync(0xffffffffu, m, o));

    // Warp sum of exp(g - m) over valid lanes.
    float e = valid ? expf(g - m) : 0.0f;
    #pragma unroll
    for (int o = 16; o > 0; o >>= 1)
        e += __shfl_xor_sync(0xffffffffu, e, o);

    if (take) {
        const float logp = la - (m + logf(e));
        atomicAdd(&out[b], logp);
    }
}

extern "C" void kernel_launch(void* const* d_in, const int* in_sizes, int n_in,
                              void* d_out, int out_size) {
    const float* logits = (const float*)d_in[0];  // [8,512,32000] f32
    const int* a        = (const int*)d_in[1];    // [8,512]       i32
    const int* mask     = (const int*)d_in[2];    // [8,512,32]    i32
    float* out = (float*)d_out;                   // [8]           f32

    zero_out_kernel<<<1, 32>>>(out);

    const int rows = BB * SS;                 // 4096 warps
    const int threads = 256;                  // 8 warps/block
    const int blocks = rows / (threads / 32); // 512 blocks
    masked_logp_kernel<<<blocks, threads>>>(logits, a, mask, out);
}

// round 7
// speedup vs baseline: 1.4910x; 1.4910x over previous
#include <cuda_runtime.h>
#include <cstdint>

// Problem shape (fixed by the reference): B=8, S=512, V=32000, M=32, PAD_ID=1
// NOTE: jax without x64 silently makes "int64" inputs int32 — a and mask are int32.
#define BB 8
#define SS 512
#define VV 32000
#define MM 32
#define PAD_ID 1

#define ROWS (BB * SS)          // 4096
#define THREADS 1024            // 32 warps/block
#define ROWS_PER_BLOCK 32
#define NBLOCKS (ROWS / ROWS_PER_BLOCK)   // 128
#define PARTIALS_PER_B (NBLOCKS / BB)     // 16

// Per-block partial sums (no device-side allocation allowed -> __device__ global).
__device__ float g_partials[NBLOCKS];

// One warp per (b,s) row. Lane j handles mask[b,s,j].
// logp(b,s) = logits[b,s,a] - log( sum_{j: mask_j>0} exp(logits[b,s,mask_j]) )
// Block-reduce 32 rows' logp -> g_partials[block]. All rows in a block share b.
__global__ void __launch_bounds__(THREADS, 1) masked_logp_kernel(
    const float* __restrict__ logits,   // [B,S,V] f32
    const int* __restrict__ a,          // [B,S]   i32
    const int* __restrict__ mask)       // [B,S,M] i32
{
    __shared__ float s_logp[ROWS_PER_BLOCK];

    const int warp = threadIdx.x >> 5;
    const int lane = threadIdx.x & 31;
    const int row  = blockIdx.x * ROWS_PER_BLOCK + warp;

    const float* __restrict__ lrow = logits + (size_t)row * VV;

    // Hoist the action-token chain so both DRAM rounds overlap the mask chain.
    const int ai = (lane == 0) ? __ldg(a + row) : 0;
    float la = 0.0f;
    bool take = false;
    if (lane == 0 && ai != PAD_ID) {
        take = true;
        la = __ldg(lrow + ai);
    }

    // Gather candidate logit for this lane's mask id.
    const int mid = __ldg(mask + (size_t)row * MM + lane);
    const bool valid = (mid > 0);
    float g = valid ? __ldg(lrow + mid) : -__int_as_float(0x7f800000); // -inf

    // Warp max over gathered logits.
    float m = g;
    #pragma unroll
    for (int o = 16; o > 0; o >>= 1)
        m = fmaxf(m, __shfl_xor_sync(0xffffffffu, m, o));

    // Warp sum of exp(g - m) over valid lanes.
    float e = valid ? __expf(g - m) : 0.0f;
    #pragma unroll
    for (int o = 16; o > 0; o >>= 1)
        e += __shfl_xor_sync(0xffffffffu, e, o);

    if (lane == 0)
        s_logp[warp] = take ? (la - (m + __logf(e))) : 0.0f;

    __syncthreads();

    // Warp 0 reduces the 32 per-row values -> one partial per block.
    if (warp == 0) {
        float v = s_logp[lane];
        #pragma unroll
        for (int o = 16; o > 0; o >>= 1)
            v += __shfl_xor_sync(0xffffffffu, v, o);
        if (lane == 0)
            g_partials[blockIdx.x] = v;
    }
}

// Sum 16 partials per batch element and write out[B]. Replaces the zero-init
// kernel (out is written, not accumulated).
__global__ void finalize_kernel(float* __restrict__ out) {
    const int tid = threadIdx.x;           // 0..127
    float v = g_partials[tid];
    // Segmented reduction: 16 consecutive partials per b (tid/16 == b).
    #pragma unroll
    for (int o = 8; o > 0; o >>= 1)
        v += __shfl_down_sync(0xffffffffu, v, o, 16);
    if ((tid & 15) == 0)
        out[tid >> 4] = v;
}

extern "C" void kernel_launch(void* const* d_in, const int* in_sizes, int n_in,
                              void* d_out, int out_size) {
    const float* logits = (const float*)d_in[0];  // [8,512,32000] f32
    const int* a        = (const int*)d_in[1];    // [8,512]       i32
    const int* mask     = (const int*)d_in[2];    // [8,512,32]    i32
    float* out = (float*)d_out;                   // [8]           f32

    masked_logp_kernel<<<NBLOCKS, THREADS>>>(logits, a, mask);
    finalize_kernel<<<1, 128>>>(out);
}

// round 8
// speedup vs baseline: 1.5294x; 1.0257x over previous
#include <cuda_runtime.h>
#include <cstdint>

// Problem shape (fixed by the reference): B=8, S=512, V=32000, M=32, PAD_ID=1
// NOTE: jax without x64 silently makes "int64" inputs int32 — a and mask are int32.
#define BB 8
#define SS 512
#define VV 32000
#define MM 32
#define PAD_ID 1

#define ROWS (BB * SS)          // 4096
#define THREADS 1024            // 32 warps/block
#define ROWS_PER_BLOCK 32
#define NBLOCKS (ROWS / ROWS_PER_BLOCK)   // 128
#define PARTIALS_PER_B (NBLOCKS / BB)     // 16  (consecutive blocks share b)

// Scratch (device-side allocation is forbidden -> __device__ globals).
__device__ float g_partials[NBLOCKS];
__device__ unsigned int g_done = 0;   // reset to 0 by the last block each run

// One warp per (b,s) row. Lane j handles mask[b,s,j].
// logp(b,s) = logits[b,s,a] - log( sum_{j: mask_j>0} exp(logits[b,s,mask_j]) )
// Block-reduces 32 rows' logp -> g_partials[block]; the last block to finish
// folds the 128 partials into out[8] (single-launch fused finalize).
__global__ void __launch_bounds__(THREADS, 1) masked_logp_kernel(
    const float* __restrict__ logits,   // [B,S,V] f32
    const int* __restrict__ a,          // [B,S]   i32
    const int* __restrict__ mask,       // [B,S,M] i32
    float* __restrict__ out)            // [B]     f32
{
    __shared__ float s_logp[ROWS_PER_BLOCK];
    __shared__ bool  s_last;

    const int warp = threadIdx.x >> 5;
    const int lane = threadIdx.x & 31;
    const int row  = blockIdx.x * ROWS_PER_BLOCK + warp;

    const float* __restrict__ lrow = logits + (size_t)row * VV;

    // Hoist the action-token chain so both DRAM rounds overlap.
    const int ai = (lane == 0) ? __ldg(a + row) : 0;
    float la = 0.0f;
    bool take = false;
    if (lane == 0 && ai != PAD_ID) {
        take = true;
        la = __ldg(lrow + ai);
    }

    // Gather candidate logit for this lane's mask id.
    const int mid = __ldg(mask + (size_t)row * MM + lane);
    const bool valid = (mid > 0);
    float g = valid ? __ldg(lrow + mid) : -__int_as_float(0x7f800000); // -inf

    // Warp max over gathered logits.
    float m = g;
    #pragma unroll
    for (int o = 16; o > 0; o >>= 1)
        m = fmaxf(m, __shfl_xor_sync(0xffffffffu, m, o));

    // Warp sum of exp(g - m) over valid lanes.
    float e = valid ? __expf(g - m) : 0.0f;
    #pragma unroll
    for (int o = 16; o > 0; o >>= 1)
        e += __shfl_xor_sync(0xffffffffu, e, o);

    if (lane == 0)
        s_logp[warp] = take ? (la - (m + __logf(e))) : 0.0f;

    __syncthreads();

    // Warp 0: reduce 32 per-row values -> this block's partial, publish it,
    // and determine whether we are the last block to finish.
    if (warp == 0) {
        float v = s_logp[lane];
        #pragma unroll
        for (int o = 16; o > 0; o >>= 1)
            v += __shfl_xor_sync(0xffffffffu, v, o);
        if (lane == 0) {
            g_partials[blockIdx.x] = v;
            __threadfence();
            const unsigned int prev = atomicAdd(&g_done, 1u);
            s_last = (prev == NBLOCKS - 1);
        }
    }
    __syncthreads();

    // Last block folds all partials into out[8] and resets the counter.
    if (s_last) {
        __threadfence();  // acquire side: make all g_partials writes visible
        const int tid = threadIdx.x;
        if (tid < NBLOCKS) {
            float v = g_partials[tid];
            // 16 consecutive partials per batch element; segments lie within a warp.
            #pragma unroll
            for (int o = 8; o > 0; o >>= 1)
                v += __shfl_down_sync(0xffffffffu, v, o, 16);
            if ((tid & 15) == 0)
                out[tid >> 4] = v;
        }
        if (tid == 0)
            g_done = 0;   // deterministic across graph replays
    }
}

extern "C" void kernel_launch(void* const* d_in, const int* in_sizes, int n_in,
                              void* d_out, int out_size) {
    const float* logits = (const float*)d_in[0];  // [8,512,32000] f32
    const int* a        = (const int*)d_in[1];    // [8,512]       i32
    const int* mask     = (const int*)d_in[2];    // [8,512,32]    i32
    float* out = (float*)d_out;                   // [8]           f32

    masked_logp_kernel<<<NBLOCKS, THREADS>>>(logits, a, mask, out);
}